// round 2
// baseline (speedup 1.0000x reference)
#include <cuda_runtime.h>

#define MASK_PAD (-4294967295.0f)

// ---- shared memory layout (float offsets) ----
#define SM_MT    0          // M^T : 128 cols x 130 (padded)  = 16640
#define SM_W1T   16640      // W1^T: 64 x 130                 = 8320
#define SM_K     24960      // K tile: 64 x 128               = 8192
#define SM_H0    33152      // H0 tile: 64 x 128              = 8192
#define SM_Q     41344      // 128
#define SM_C     41472      // 128
#define SM_B1    41600      // 64
#define SM_WOUT  41664      // 64
#define SM_LOG   41728      // 208 (200 used)
#define SM_RED   41936      // 64
#define SM_TOTF  42016      // total floats -> 168064 bytes

__device__ float g_W0bc[128 * 128];   // W0b - W0c
__device__ float g_W0ac[128 * 128];   // W0a + W0c

__global__ void prep_kernel(const float* __restrict__ W0) {
    int idx = blockIdx.x * blockDim.x + threadIdx.x;
    if (idx < 128 * 128) {
        int i = idx >> 7, j = idx & 127;
        float wa = W0[i * 128 + j];
        float wb = W0[(128 + i) * 128 + j];
        float wc = W0[(256 + i) * 128 + j];
        g_W0bc[idx] = wb - wc;
        g_W0ac[idx] = wa + wc;
    }
}

// packed fp32x2 FMA (Blackwell): d = a*b + d on both halves
__device__ __forceinline__ void fma2(unsigned long long& d,
                                     unsigned long long a,
                                     unsigned long long b) {
    asm("fma.rn.f32x2 %0, %1, %2, %0;" : "+l"(d) : "l"(a), "l"(b));
}
__device__ __forceinline__ float psum(unsigned long long v) {
    return __uint_as_float((unsigned)(v & 0xffffffffu)) +
           __uint_as_float((unsigned)(v >> 32));
}

__global__ void __launch_bounds__(256, 1)
din_kernel(const float* __restrict__ query, const float* __restrict__ key,
           const float* __restrict__ val, const int* __restrict__ mask,
           const float* __restrict__ W0, const float* __restrict__ b0,
           const float* __restrict__ a0, const float* __restrict__ W1,
           const float* __restrict__ b1, const float* __restrict__ a1,
           const float* __restrict__ Wout, const float* __restrict__ bout,
           float* __restrict__ out) {
    extern __shared__ float sm[];
    const int tid = threadIdx.x;
    const int lane = tid & 31;
    const int w = tid >> 5;
    const int b = blockIdx.x;

    if (tid < 128) sm[SM_Q + tid] = query[(size_t)b * 128 + tid];
    if (tid < 64) {
        sm[SM_B1 + tid] = b1[tid];
        sm[SM_WOUT + tid] = Wout[tid];
    }
    __syncthreads();

    // Build M^T = (W0b - W0c + diag(q) W0d)^T  (stride 130 to soften conflicts)
    const float* W0d = W0 + 384 * 128;
    for (int p = 0; p < 64; p++) {
        int idx = tid + p * 256;
        int i = idx >> 7, j = idx & 127;
        sm[SM_MT + j * 130 + i] = g_W0bc[idx] + sm[SM_Q + i] * W0d[idx];
    }
    // W1^T
    for (int p = 0; p < 32; p++) {
        int idx = tid + p * 256;
        int c = idx >> 6, g = idx & 63;
        sm[SM_W1T + g * 130 + c] = W1[idx];
    }
    // c-vector: q @ (W0a + W0c) + b0
    if (tid < 128) {
        float s0 = 0.f, s1 = 0.f, s2 = 0.f, s3 = 0.f;
        for (int i = 0; i < 128; i += 4) {
            s0 += sm[SM_Q + i + 0] * g_W0ac[(i + 0) * 128 + tid];
            s1 += sm[SM_Q + i + 1] * g_W0ac[(i + 1) * 128 + tid];
            s2 += sm[SM_Q + i + 2] * g_W0ac[(i + 2) * 128 + tid];
            s3 += sm[SM_Q + i + 3] * g_W0ac[(i + 3) * 128 + tid];
        }
        sm[SM_C + tid] = (s0 + s1) + (s2 + s3) + b0[tid];
    }
    __syncthreads();

    // ---- main loop over 4 row-tiles of 64 ----
    for (int tile = 0; tile < 4; tile++) {
        const int base = tile * 64;

        // load K tile (float4, coalesced)
        #pragma unroll
        for (int p = 0; p < 8; p++) {
            int f = tid + p * 256;
            int row = f >> 5;
            int c4 = (f & 31) << 2;
            int t = base + row;
            float4 v;
            if (t < 200)
                v = *(const float4*)&key[((size_t)b * 200 + t) * 128 + c4];
            else
                v = make_float4(0.f, 0.f, 0.f, 0.f);
            *(float4*)&sm[SM_K + row * 128 + c4] = v;
        }
        __syncthreads();

        int nrows = 200 - base;
        if (nrows > 64) nrows = 64;
        const bool active = (w * 8) < nrows;  // nrows is 64 or 8 -> whole warps

        // GEMM1: H0 = K @ M + c, PReLU(a0)
        if (active) {
            unsigned long long acc[8][4];
            #pragma unroll
            for (int r = 0; r < 8; r++)
                #pragma unroll
                for (int j = 0; j < 4; j++) acc[r][j] = 0ull;

            const float* kb = &sm[SM_K + (w * 8) * 128];
            #pragma unroll 4
            for (int kk = 0; kk < 128; kk += 4) {
                unsigned long long kv0[8], kv1[8];
                #pragma unroll
                for (int r = 0; r < 8; r++) {
                    ulonglong2 t2 = *(const ulonglong2*)(kb + r * 128 + kk);
                    kv0[r] = t2.x;
                    kv1[r] = t2.y;
                }
                #pragma unroll
                for (int j = 0; j < 4; j++) {
                    const float* mb = &sm[SM_MT + (lane + 32 * j) * 130 + kk];
                    unsigned long long m0 = *(const unsigned long long*)(mb);
                    unsigned long long m1 = *(const unsigned long long*)(mb + 2);
                    #pragma unroll
                    for (int r = 0; r < 8; r++) {
                        fma2(acc[r][j], kv0[r], m0);
                        fma2(acc[r][j], kv1[r], m1);
                    }
                }
            }
            #pragma unroll
            for (int r = 0; r < 8; r++) {
                const int t = base + w * 8 + r;
                #pragma unroll
                for (int j = 0; j < 4; j++) {
                    const int c = lane + 32 * j;
                    float x = psum(acc[r][j]) + sm[SM_C + c];
                    if (x < 0.f) x *= a0[t * 128 + c];
                    sm[SM_H0 + (w * 8 + r) * 128 + c] = x;
                }
            }
        }
        __syncthreads();

        // GEMM2: H1 = H0 @ W1 + b1, PReLU(a1); logits via warp reduce
        if (active) {
            unsigned long long acc2[8][2];
            #pragma unroll
            for (int r = 0; r < 8; r++) {
                acc2[r][0] = 0ull;
                acc2[r][1] = 0ull;
            }
            const float* hb = &sm[SM_H0 + (w * 8) * 128];
            #pragma unroll 4
            for (int cc = 0; cc < 128; cc += 4) {
                unsigned long long av0[8], av1[8];
                #pragma unroll
                for (int r = 0; r < 8; r++) {
                    ulonglong2 t2 = *(const ulonglong2*)(hb + r * 128 + cc);
                    av0[r] = t2.x;
                    av1[r] = t2.y;
                }
                #pragma unroll
                for (int j = 0; j < 2; j++) {
                    const float* wb2 = &sm[SM_W1T + (lane + 32 * j) * 130 + cc];
                    unsigned long long w0 = *(const unsigned long long*)(wb2);
                    unsigned long long w1 = *(const unsigned long long*)(wb2 + 2);
                    #pragma unroll
                    for (int r = 0; r < 8; r++) {
                        fma2(acc2[r][j], av0[r], w0);
                        fma2(acc2[r][j], av1[r], w1);
                    }
                }
            }
            #pragma unroll
            for (int r = 0; r < 8; r++) {
                const int t = base + w * 8 + r;
                float part = 0.f;
                #pragma unroll
                for (int j = 0; j < 2; j++) {
                    const int g = lane + 32 * j;
                    float x = psum(acc2[r][j]) + sm[SM_B1 + g];
                    if (x < 0.f) x *= a1[t * 64 + g];
                    part += x * sm[SM_WOUT + g];
                }
                #pragma unroll
                for (int o = 16; o > 0; o >>= 1)
                    part += __shfl_xor_sync(0xffffffffu, part, o);
                if (lane == 0) {
                    float lg = part + bout[0];
                    if (mask[(size_t)b * 200 + t] == 0) lg = MASK_PAD;
                    sm[SM_LOG + t] = lg;
                }
            }
        }
        __syncthreads();
    }

    // ---- softmax over 200 logits ----
    float v = (tid < 200) ? sm[SM_LOG + tid] : -3.4e38f;
    float m = v;
    #pragma unroll
    for (int o = 16; o > 0; o >>= 1)
        m = fmaxf(m, __shfl_xor_sync(0xffffffffu, m, o));
    if (lane == 0) sm[SM_RED + w] = m;
    __syncthreads();
    float mx = sm[SM_RED + 0];
    #pragma unroll
    for (int i = 1; i < 8; i++) mx = fmaxf(mx, sm[SM_RED + i]);
    float e = (tid < 200) ? expf(v - mx) : 0.f;
    float s = e;
    #pragma unroll
    for (int o = 16; o > 0; o >>= 1)
        s += __shfl_xor_sync(0xffffffffu, s, o);
    __syncthreads();  // SM_RED reads done before re-writing
    if (lane == 0) sm[SM_RED + w] = s;
    __syncthreads();
    float tot = 0.f;
    #pragma unroll
    for (int i = 0; i < 8; i++) tot += sm[SM_RED + i];
    if (tid < 200) sm[SM_LOG + tid] = e / tot;
    __syncthreads();

    // ---- out[b, :] = attn @ V  (two halves of t, 128 d-lanes each) ----
    const int half = tid >> 7;
    const int d = tid & 127;
    const float* vb = val + ((size_t)b * 200 + half * 100) * 128 + d;
    const float* at = &sm[SM_LOG + half * 100];
    float s0 = 0.f, s1 = 0.f, s2 = 0.f, s3 = 0.f;
    for (int t = 0; t < 100; t += 4) {
        s0 += at[t + 0] * vb[(size_t)(t + 0) * 128];
        s1 += at[t + 1] * vb[(size_t)(t + 1) * 128];
        s2 += at[t + 2] * vb[(size_t)(t + 2) * 128];
        s3 += at[t + 3] * vb[(size_t)(t + 3) * 128];
    }
    float sv = (s0 + s1) + (s2 + s3);
    sm[SM_K + tid] = sv;   // SM_K region is free now
    __syncthreads();
    if (tid < 128)
        out[(size_t)b * 128 + tid] = sm[SM_K + tid] + sm[SM_K + 128 + tid];
}

extern "C" void kernel_launch(void* const* d_in, const int* in_sizes, int n_in,
                              void* d_out, int out_size) {
    (void)in_sizes; (void)n_in; (void)out_size;
    const float* query = (const float*)d_in[0];
    const float* key   = (const float*)d_in[1];
    const float* val   = (const float*)d_in[2];
    const int*   mask  = (const int*)d_in[3];
    const float* W0    = (const float*)d_in[4];
    const float* b0    = (const float*)d_in[5];
    const float* a0    = (const float*)d_in[6];
    const float* W1    = (const float*)d_in[7];
    const float* b1    = (const float*)d_in[8];
    const float* a1    = (const float*)d_in[9];
    const float* Wout  = (const float*)d_in[10];
    const float* bout  = (const float*)d_in[11];
    float* out = (float*)d_out;

    cudaFuncSetAttribute(din_kernel, cudaFuncAttributeMaxDynamicSharedMemorySize,
                         SM_TOTF * 4);
    prep_kernel<<<64, 256>>>(W0);
    din_kernel<<<2048, 256, SM_TOTF * 4>>>(query, key, val, mask, W0, b0, a0,
                                           W1, b1, a1, Wout, bout, out);
}